// round 8
// baseline (speedup 1.0000x reference)
#include <cuda_runtime.h>
#include <cstdint>
#include <math.h>

// CausalGRNEMA exact chunked scan, mixed granularity:
//  pass1: LC1=64 warp chunks, stores half-chunk (32-step) AND full aggregates
//  pass2: serial combine -> exact carry-in at 32-step granularity (+ g_tab)
//  pass3: LC3=32 warp chunks, register 1-deep prefetch, __launch_bounds__(256,3)
//         -> ~24 warps/SM for latency hiding; channel mean warp-internal.
// State scaled: f = ema/OMA, f' = alpha*f + x^2.

#define ALPHA   0.99f
#define OMA     0.01f
#define EPSF    1e-6f
#define EMAINIT 1e-4f

static constexpr int B   = 16;
static constexpr int T   = 8192;
static constexpr int C   = 512;
static constexpr int C4  = C / 4;           // 128 float4 columns
static constexpr int LC1 = 64;              // pass1 chunk
static constexpr int NCH1 = T / LC1;        // 128
static constexpr int LC3 = 32;              // pass3 chunk
static constexpr int NCH3 = T / LC3;        // 256
static constexpr int WPB = 8;
static constexpr int NTASK1 = B * NCH1;     // 2048
static constexpr int NTASK3 = B * NCH3;     // 4096

__device__ float2 g_tab[T];                 // (EPS*D_t, EPS*sqrt(D_t))
__device__ float  g_Sf[NTASK1 * C];         // full-chunk aggregates (64 steps)
__device__ float  g_Sh[NTASK1 * C];         // half-chunk aggregates (32 steps)
__device__ float  g_Ein[NTASK3 * C];        // exact carry-in per 32-chunk

// ---- pass1: warp-autonomous local scan, half+full aggregates ----
__global__ __launch_bounds__(256, 3)
void pass1_kernel(const float* __restrict__ x) {
    const int warp = threadIdx.x >> 5;
    const int lane = threadIdx.x & 31;
    const int task = blockIdx.x * WPB + warp;
    const int b = task >> 7;                // / NCH1 (=128)
    const int k = task & (NCH1 - 1);

    const float4* __restrict__ xb =
        (const float4*)x + ((size_t)b * T + (size_t)k * LC1) * C4 + lane;
    float4* __restrict__ Sh4 = (float4*)g_Sh + (size_t)task * C4 + lane;

    float4 f[4], cur[4], nxt[4];
    #pragma unroll
    for (int j = 0; j < 4; j++) f[j] = make_float4(0.f, 0.f, 0.f, 0.f);
    #pragma unroll
    for (int j = 0; j < 4; j++) cur[j] = xb[j * 32];

    for (int t = 0; t < LC1; t++) {
        if (t + 1 < LC1) {
            #pragma unroll
            for (int j = 0; j < 4; j++) nxt[j] = xb[(size_t)(t + 1) * C4 + j * 32];
        }
        #pragma unroll
        for (int j = 0; j < 4; j++) {
            f[j].x = fmaf(ALPHA, f[j].x, cur[j].x * cur[j].x);
            f[j].y = fmaf(ALPHA, f[j].y, cur[j].y * cur[j].y);
            f[j].z = fmaf(ALPHA, f[j].z, cur[j].z * cur[j].z);
            f[j].w = fmaf(ALPHA, f[j].w, cur[j].w * cur[j].w);
        }
        if (t == LC3 - 1) {                 // half-chunk aggregate
            #pragma unroll
            for (int j = 0; j < 4; j++) Sh4[j * 32] = f[j];
        }
        #pragma unroll
        for (int j = 0; j < 4; j++) cur[j] = nxt[j];
    }
    float4* __restrict__ Sf4 = (float4*)g_Sf + (size_t)task * C4 + lane;
    #pragma unroll
    for (int j = 0; j < 4; j++) Sf4[j * 32] = f[j];
}

// ---- pass2: build g_tab + exact carry combine at 32-step granularity ----
__global__ void pass2_kernel() {
    const int idx = blockIdx.x * blockDim.x + threadIdx.x;  // 0..B*C-1 (== T)
    if (idx < T) {
        double D = 1.0 - exp((double)(idx + 1) * log(0.99)) + 1e-6;
        g_tab[idx] = make_float2((float)(1e-6 * D), (float)(1e-6 * sqrt(D)));
    }
    if (idx >= B * C) return;
    const int b = idx / C;
    const int c = idx % C;
    const float a32 = (float)exp(32.0 * log(0.99));
    const float a64 = a32 * a32;
    float E = EMAINIT / OMA;                // f-units
    #pragma unroll 4
    for (int k = 0; k < NCH1; k++) {
        const size_t o1 = ((size_t)b * NCH1 + k) * C + c;
        const size_t o3 = ((size_t)b * NCH3 + 2 * k) * C + c;
        g_Ein[o3]     = E;
        g_Ein[o3 + C] = fmaf(a32, E, g_Sh[o1]);
        E = fmaf(a64, E, g_Sf[o1]);
    }
}

// ---- pass3: warp-autonomous rescan (LC3=32), high occupancy ----
__global__ __launch_bounds__(256, 3)
void pass3_kernel(const float* __restrict__ x,
                  const float* __restrict__ gamma,
                  const float* __restrict__ beta,
                  float* __restrict__ y) {
    __shared__ float4 sg[C4], sb[C4];
    {
        const int tid = threadIdx.x;
        if (tid < C4)       sg[tid]      = ((const float4*)gamma)[tid];
        else                sb[tid - C4] = ((const float4*)beta)[tid - C4];
    }
    __syncthreads();   // once

    const int warp = threadIdx.x >> 5;
    const int lane = threadIdx.x & 31;
    const int task = blockIdx.x * WPB + warp;
    const int b = task >> 8;                // / NCH3 (=256)
    const int k = task & (NCH3 - 1);
    const int tbase = k * LC3;

    const float4* __restrict__ xb =
        (const float4*)x + ((size_t)b * T + tbase) * C4 + lane;
    float4* __restrict__ yb =
        (float4*)y + ((size_t)b * T + tbase) * C4 + lane;

    float4 f[4];
    {
        const float4* __restrict__ E4 = (const float4*)g_Ein + (size_t)task * C4 + lane;
        #pragma unroll
        for (int j = 0; j < 4; j++) f[j] = E4[j * 32];
    }

    float4 cur[4], nxt[4];
    #pragma unroll
    for (int j = 0; j < 4; j++) cur[j] = xb[j * 32];

    float2 cs = g_tab[tbase];

    for (int t = 0; t < LC3; t++) {
        if (t + 1 < LC3) {
            #pragma unroll
            for (int j = 0; j < 4; j++) nxt[j] = xb[(size_t)(t + 1) * C4 + j * 32];
        }
        const float2 csn = g_tab[(tbase + t + 1 < T) ? (tbase + t + 1) : (T - 1)];

        float4 s[4];
        float acc = 0.0f;
        #pragma unroll
        for (int j = 0; j < 4; j++) {
            f[j].x = fmaf(ALPHA, f[j].x, cur[j].x * cur[j].x);
            f[j].y = fmaf(ALPHA, f[j].y, cur[j].y * cur[j].y);
            f[j].z = fmaf(ALPHA, f[j].z, cur[j].z * cur[j].z);
            f[j].w = fmaf(ALPHA, f[j].w, cur[j].w * cur[j].w);
            float vx = fmaf(OMA, f[j].x, cs.x);
            float vy = fmaf(OMA, f[j].y, cs.x);
            float vz = fmaf(OMA, f[j].z, cs.x);
            float vw = fmaf(OMA, f[j].w, cs.x);
            s[j].x = __frsqrt_rn(vx) * vx;  // = sqrt(vx)
            s[j].y = __frsqrt_rn(vy) * vy;
            s[j].z = __frsqrt_rn(vz) * vz;
            s[j].w = __frsqrt_rn(vw) * vw;
            acc += (s[j].x + s[j].y) + (s[j].z + s[j].w);
        }
        acc += __shfl_xor_sync(0xffffffffu, acc, 16);
        acc += __shfl_xor_sync(0xffffffffu, acc, 8);
        acc += __shfl_xor_sync(0xffffffffu, acc, 4);
        acc += __shfl_xor_sync(0xffffffffu, acc, 2);
        acc += __shfl_xor_sync(0xffffffffu, acc, 1);

        // inv-independent epilogue terms overlap the shfl chain:
        //   y = a*inv + d,  a = x*gamma*s,  d = x + beta
        float4 a[4], d[4];
        #pragma unroll
        for (int j = 0; j < 4; j++) {
            const float4 g4 = sg[lane + j * 32];
            const float4 b4 = sb[lane + j * 32];
            a[j].x = cur[j].x * g4.x * s[j].x;
            a[j].y = cur[j].y * g4.y * s[j].y;
            a[j].z = cur[j].z * g4.z * s[j].z;
            a[j].w = cur[j].w * g4.w * s[j].w;
            d[j].x = cur[j].x + b4.x;
            d[j].y = cur[j].y + b4.y;
            d[j].z = cur[j].z + b4.z;
            d[j].w = cur[j].w + b4.w;
        }

        const float inv = __fdividef(1.0f, fmaf(acc, 1.0f / C, cs.y));

        #pragma unroll
        for (int j = 0; j < 4; j++) {
            float4 o;
            o.x = fmaf(a[j].x, inv, d[j].x);
            o.y = fmaf(a[j].y, inv, d[j].y);
            o.z = fmaf(a[j].z, inv, d[j].z);
            o.w = fmaf(a[j].w, inv, d[j].w);
            yb[(size_t)t * C4 + j * 32] = o;
        }

        #pragma unroll
        for (int j = 0; j < 4; j++) cur[j] = nxt[j];
        cs = csn;
    }
}

extern "C" void kernel_launch(void* const* d_in, const int* in_sizes, int n_in,
                              void* d_out, int out_size) {
    const float* x     = (const float*)d_in[0];
    const float* gamma = (const float*)d_in[1];
    const float* beta  = (const float*)d_in[2];
    float* y           = (float*)d_out;

    pass1_kernel<<<NTASK1 / WPB, 256>>>(x);
    pass2_kernel<<<(B * C + 255) / 256, 256>>>();
    pass3_kernel<<<NTASK3 / WPB, 256>>>(x, gamma, beta, y);
}

// round 9
// speedup vs baseline: 1.6500x; 1.6500x over previous
#include <cuda_runtime.h>
#include <cstdint>
#include <math.h>

// CausalGRNEMA exact chunked scan, warp-autonomous (R4 structure):
//  pass1: per-(b,chunk) warp scans LC steps from 0 -> aggregate S (f-units)
//  pass2: serial combine over chunks -> exact carry-in per chunk (+ g_tab)
//  pass3: per-(b,chunk) warp rescans with carry-in; channel mean warp-internal.
//  R9 delta vs R4: sqrt via sqrt.approx.f32 (1 MUFU) instead of the IEEE
//  __frsqrt_rn Newton sequence -> ~90 fewer issue slots per warp-timestep.
// State scaled: f = ema/OMA, f' = alpha*f + x^2.

#define ALPHA   0.99f
#define OMA     0.01f
#define EPSF    1e-6f
#define EMAINIT 1e-4f

static constexpr int B  = 16;
static constexpr int T  = 8192;
static constexpr int C  = 512;
static constexpr int C4 = C / 4;          // 128 float4 columns
static constexpr int LC = 64;             // timesteps per warp task
static constexpr int NCH = T / LC;        // 128 chunks
static constexpr int WPB = 8;             // warps per block
static constexpr int NTASK = B * NCH;     // 2048 warp tasks

__device__ float2 g_tab[T];               // (EPS*D_t, EPS*sqrt(D_t))
__device__ float  g_S[NTASK * C];         // chunk aggregates (f-units)
__device__ float  g_Ein[NTASK * C];       // exact carry-in per chunk (f-units)

__device__ __forceinline__ float fast_sqrt(float v) {
    float r;
    asm("sqrt.approx.f32 %0, %1;" : "=f"(r) : "f"(v));
    return r;
}

// ---- pass1: warp-autonomous local scan, aggregate only ----
__global__ __launch_bounds__(256, 3)
void pass1_kernel(const float* __restrict__ x) {
    const int warp = threadIdx.x >> 5;
    const int lane = threadIdx.x & 31;
    const int task = blockIdx.x * WPB + warp;
    const int b = task >> 7;              // / NCH
    const int k = task & (NCH - 1);

    const float4* __restrict__ xb =
        (const float4*)x + ((size_t)b * T + (size_t)k * LC) * C4 + lane;

    float4 f[4], cur[4], nxt[4];
    #pragma unroll
    for (int j = 0; j < 4; j++) f[j] = make_float4(0.f, 0.f, 0.f, 0.f);
    #pragma unroll
    for (int j = 0; j < 4; j++) cur[j] = xb[j * 32];

    for (int t = 0; t < LC; t++) {
        if (t + 1 < LC) {
            #pragma unroll
            for (int j = 0; j < 4; j++) nxt[j] = xb[(size_t)(t + 1) * C4 + j * 32];
        }
        #pragma unroll
        for (int j = 0; j < 4; j++) {
            f[j].x = fmaf(ALPHA, f[j].x, cur[j].x * cur[j].x);
            f[j].y = fmaf(ALPHA, f[j].y, cur[j].y * cur[j].y);
            f[j].z = fmaf(ALPHA, f[j].z, cur[j].z * cur[j].z);
            f[j].w = fmaf(ALPHA, f[j].w, cur[j].w * cur[j].w);
        }
        #pragma unroll
        for (int j = 0; j < 4; j++) cur[j] = nxt[j];
    }
    float4* __restrict__ S4 = (float4*)g_S + (size_t)task * C4 + lane;
    #pragma unroll
    for (int j = 0; j < 4; j++) S4[j * 32] = f[j];
}

// ---- pass2: build g_tab + exact carry combine across chunks ----
__global__ void pass2_kernel() {
    const int idx = blockIdx.x * blockDim.x + threadIdx.x;  // 0..B*C-1 (== T)
    if (idx < T) {
        double D = 1.0 - exp((double)(idx + 1) * log(0.99)) + 1e-6;
        g_tab[idx] = make_float2((float)(1e-6 * D), (float)(1e-6 * sqrt(D)));
    }
    if (idx >= B * C) return;
    const int b = idx / C;
    const int c = idx % C;
    const float aL = (float)exp((double)LC * log(0.99));
    float E = EMAINIT / OMA;              // f-units
    #pragma unroll 8
    for (int k = 0; k < NCH; k++) {
        const size_t o = ((size_t)b * NCH + k) * C + c;
        g_Ein[o] = E;
        E = fmaf(aL, E, g_S[o]);
    }
}

// ---- pass3: warp-autonomous rescan + warp-internal channel mean + epilogue ----
__global__ __launch_bounds__(256, 2)
void pass3_kernel(const float* __restrict__ x,
                  const float* __restrict__ gamma,
                  const float* __restrict__ beta,
                  float* __restrict__ y) {
    __shared__ float4 sg[C4], sb[C4];
    {
        const int tid = threadIdx.x;
        if (tid < C4)       sg[tid]      = ((const float4*)gamma)[tid];
        else                sb[tid - C4] = ((const float4*)beta)[tid - C4];
    }
    __syncthreads();   // once

    const int warp = threadIdx.x >> 5;
    const int lane = threadIdx.x & 31;
    const int task = blockIdx.x * WPB + warp;
    const int b = task >> 7;
    const int k = task & (NCH - 1);
    const int tbase = k * LC;

    const float4* __restrict__ xb =
        (const float4*)x + ((size_t)b * T + tbase) * C4 + lane;
    float4* __restrict__ yb =
        (float4*)y + ((size_t)b * T + tbase) * C4 + lane;

    float4 f[4];
    {
        const float4* __restrict__ E4 = (const float4*)g_Ein + (size_t)task * C4 + lane;
        #pragma unroll
        for (int j = 0; j < 4; j++) f[j] = E4[j * 32];
    }

    float4 cur[4], nxt[4];
    #pragma unroll
    for (int j = 0; j < 4; j++) cur[j] = xb[j * 32];

    for (int t = 0; t < LC; t++) {
        if (t + 1 < LC) {
            #pragma unroll
            for (int j = 0; j < 4; j++) nxt[j] = xb[(size_t)(t + 1) * C4 + j * 32];
        }
        const float2 cs = g_tab[tbase + t];   // (EPS*D, EPS*sqrt(D))

        float4 s[4];
        float acc = 0.0f;
        #pragma unroll
        for (int j = 0; j < 4; j++) {
            f[j].x = fmaf(ALPHA, f[j].x, cur[j].x * cur[j].x);
            f[j].y = fmaf(ALPHA, f[j].y, cur[j].y * cur[j].y);
            f[j].z = fmaf(ALPHA, f[j].z, cur[j].z * cur[j].z);
            f[j].w = fmaf(ALPHA, f[j].w, cur[j].w * cur[j].w);
            s[j].x = fast_sqrt(fmaf(OMA, f[j].x, cs.x));
            s[j].y = fast_sqrt(fmaf(OMA, f[j].y, cs.x));
            s[j].z = fast_sqrt(fmaf(OMA, f[j].z, cs.x));
            s[j].w = fast_sqrt(fmaf(OMA, f[j].w, cs.x));
            acc += (s[j].x + s[j].y) + (s[j].z + s[j].w);
        }
        acc += __shfl_xor_sync(0xffffffffu, acc, 16);
        acc += __shfl_xor_sync(0xffffffffu, acc, 8);
        acc += __shfl_xor_sync(0xffffffffu, acc, 4);
        acc += __shfl_xor_sync(0xffffffffu, acc, 2);
        acc += __shfl_xor_sync(0xffffffffu, acc, 1);

        // n_c = s_c / (mean + EPS*sqrt(D)); y = x*(1 + gamma*n) + beta
        const float inv = __fdividef(1.0f, fmaf(acc, 1.0f / C, cs.y));

        #pragma unroll
        for (int j = 0; j < 4; j++) {
            const float4 g4 = sg[lane + j * 32];
            const float4 b4 = sb[lane + j * 32];
            float4 o;
            o.x = fmaf(cur[j].x, fmaf(g4.x, s[j].x * inv, 1.0f), b4.x);
            o.y = fmaf(cur[j].y, fmaf(g4.y, s[j].y * inv, 1.0f), b4.y);
            o.z = fmaf(cur[j].z, fmaf(g4.z, s[j].z * inv, 1.0f), b4.z);
            o.w = fmaf(cur[j].w, fmaf(g4.w, s[j].w * inv, 1.0f), b4.w);
            yb[(size_t)t * C4 + j * 32] = o;
        }
        #pragma unroll
        for (int j = 0; j < 4; j++) cur[j] = nxt[j];
    }
}

extern "C" void kernel_launch(void* const* d_in, const int* in_sizes, int n_in,
                              void* d_out, int out_size) {
    const float* x     = (const float*)d_in[0];
    const float* gamma = (const float*)d_in[1];
    const float* beta  = (const float*)d_in[2];
    float* y           = (float*)d_out;

    pass1_kernel<<<NTASK / WPB, 256>>>(x);
    pass2_kernel<<<(B * C + 255) / 256, 256>>>();
    pass3_kernel<<<NTASK / WPB, 256>>>(x, gamma, beta, y);
}